// round 1
// baseline (speedup 1.0000x reference)
#include <cuda_runtime.h>

#define BMAX 16384
#define L 16
#define D 8
#define U 128
#define P 8

// ---- composed-weight + softmax scratch (static device arrays; no allocs) ----
__device__ float g_WqT[D*U],  g_bq[U];   // sq_w composed with le_w (transposed [d][u])
__device__ float g_WrT[D*U],  g_br[U];   // sr_w composed
__device__ float g_WaqT[D*U], g_caq[U];  // aq_w composed (caq = aq_w@le_b)
__device__ float g_WarT[D*U], g_car[U];  // ar_w composed
__device__ float g_logits[(size_t)BMAX*L];
__device__ float g_invden[L];

__device__ __forceinline__ float fast_tanh(float x) {
    // 1 - 2/(e^{2x}+1): stable at both saturations (inf -> 1, 0 -> -1), rel err ~1e-6
    float e = __expf(2.0f * x);
    return 1.0f - __fdividef(2.0f, e + 1.0f);
}

// ---------------------------------------------------------------------------
// Kernel 0: fold le_w/le_b through the four 128x128 linears.
// grid.x = 4 (matrix id), 128 threads (one output unit u each).
// WT[d*U+u] = sum_k W[u][k] * le_w[k][d];  bias terms folded per-matrix.
// ---------------------------------------------------------------------------
__global__ void k_compose(const float* __restrict__ le_w, const float* __restrict__ le_b,
                          const float* __restrict__ sq_w, const float* __restrict__ sq_b,
                          const float* __restrict__ sr_w, const float* __restrict__ sr_b,
                          const float* __restrict__ aq_w,
                          const float* __restrict__ ar_w) {
    __shared__ float sle[U*D], sleb[U];
    int u = threadIdx.x;
#pragma unroll
    for (int d = 0; d < D; d++) sle[u*D + d] = le_w[u*D + d];
    sleb[u] = le_b[u];
    __syncthreads();

    int m = blockIdx.x;
    const float* W = (m == 0) ? sq_w : (m == 1) ? sr_w : (m == 2) ? aq_w : ar_w;

    float acc[D];
#pragma unroll
    for (int d = 0; d < D; d++) acc[d] = 0.0f;
    float ab = 0.0f;
    for (int k = 0; k < U; k++) {
        float w = W[u*U + k];
        ab = fmaf(w, sleb[k], ab);
#pragma unroll
        for (int d = 0; d < D; d++) acc[d] = fmaf(w, sle[k*D + d], acc[d]);
    }
    float* WT = (m == 0) ? g_WqT : (m == 1) ? g_WrT : (m == 2) ? g_WaqT : g_WarT;
#pragma unroll
    for (int d = 0; d < D; d++) WT[d*U + u] = acc[d];
    if      (m == 0) g_bq[u]  = ab + sq_b[u];
    else if (m == 1) g_br[u]  = ab + sr_b[u];
    else if (m == 2) g_caq[u] = ab;
    else             g_car[u] = ab;
}

// ---------------------------------------------------------------------------
// Kernel 1: attention logits. One warp per batch element, 8 warps/block.
// Each lane owns 4 of the 128 hidden units (u = lane + 32j).
// logit[b][l] = sa_b + sum_u tanh(ref[u] + xq[l][u]) * sa_w[u]
// ---------------------------------------------------------------------------
__global__ void __launch_bounds__(256) k_logits(const float* __restrict__ states,
                                                const float* __restrict__ sa_w,
                                                const float* __restrict__ sa_b, int B) {
    __shared__ float sx[8][L*D];
    __shared__ float slog[8][L];
    int warp = threadIdx.x >> 5, lane = threadIdx.x & 31;
    int b = blockIdx.x * 8 + warp;
    if (b >= B) return;

    const float* xs = states + (size_t)b * (L*D + 1) + 1;
#pragma unroll
    for (int i = 0; i < 4; i++) sx[warp][lane + 32*i] = xs[lane + 32*i];
    __syncwarp();

    // mean over the 16 lanes (per input dim d), computed on lanes 0..7, broadcast
    float mv = 0.0f;
    if (lane < D) {
#pragma unroll
        for (int l = 0; l < L; l++) mv += sx[warp][l*D + lane];
        mv *= (1.0f / 16.0f);
    }
    float mean[D];
#pragma unroll
    for (int d = 0; d < D; d++) mean[d] = __shfl_sync(0xffffffffu, mv, d);

    // ref = mean @ WrT + br  (4 units per lane)
    float ref[4];
#pragma unroll
    for (int j = 0; j < 4; j++) {
        int u = lane + 32*j;
        float r = g_br[u];
#pragma unroll
        for (int d = 0; d < D; d++) r = fmaf(mean[d], g_WrT[d*U + u], r);
        ref[j] = r;
    }

    // register-resident query weights + sa_w
    float wq[4][D], bq[4], sw[4];
#pragma unroll
    for (int j = 0; j < 4; j++) {
        int u = lane + 32*j;
        bq[j] = g_bq[u];
        sw[j] = sa_w[u];
#pragma unroll
        for (int d = 0; d < D; d++) wq[j][d] = g_WqT[d*U + u];
    }
    float sab = *sa_b;

#pragma unroll
    for (int l = 0; l < L; l++) {
        float xl[D];
#pragma unroll
        for (int d = 0; d < D; d++) xl[d] = sx[warp][l*D + d];
        float acc = 0.0f;
#pragma unroll
        for (int j = 0; j < 4; j++) {
            float q = bq[j];
#pragma unroll
            for (int d = 0; d < D; d++) q = fmaf(xl[d], wq[j][d], q);
            acc = fmaf(fast_tanh(ref[j] + q), sw[j], acc);
        }
#pragma unroll
        for (int o = 16; o > 0; o >>= 1) acc += __shfl_down_sync(0xffffffffu, acc, o);
        if (lane == 0) slog[warp][l] = acc + sab;
    }
    __syncwarp();
    if (lane < L) g_logits[(size_t)b*L + lane] = slog[warp][lane];
}

// ---------------------------------------------------------------------------
// Kernel 2: softmax denominator over the BATCH axis (one block per lane l).
// Deterministic tree reduction; max-subtraction skipped (logits O(±5)).
// ---------------------------------------------------------------------------
__global__ void k_softmax_den(int B) {
    int l = blockIdx.x;
    int tid = threadIdx.x;
    float s = 0.0f;
    for (int b = tid; b < B; b += 256) s += __expf(g_logits[(size_t)b*L + l]);
    __shared__ float red[256];
    red[tid] = s;
    __syncthreads();
    for (int o = 128; o > 0; o >>= 1) {
        if (tid < o) red[tid] += red[tid + o];
        __syncthreads();
    }
    if (tid == 0) g_invden[l] = 1.0f / red[0];
}

// ---------------------------------------------------------------------------
// Kernel 3: output. One warp per batch element.
// a[l] = exp(logit)/den;  y_p = a_i0*x_i0 + a_i1*x_i1 (8-dim);  s_p = a_i0+a_i1
// green = y_phase@WarT + s_phase*car + ar_b
// q[b][p] = aa_b + sum_u tanh(y_p@WaqT + s_p*caq + aq_b + green)[u] * aa_w[u]
// ---------------------------------------------------------------------------
__global__ void __launch_bounds__(256) k_out(const float* __restrict__ states,
                                             const float* __restrict__ aq_b,
                                             const float* __restrict__ ar_b,
                                             const float* __restrict__ aa_w,
                                             const float* __restrict__ aa_b,
                                             const int*   __restrict__ pp,
                                             float* __restrict__ out, int B) {
    __shared__ float sx[8][L*D];
    __shared__ float sat[8][L];
    __shared__ float sy[8][P][D];
    __shared__ float ssum[8][P];
    __shared__ float sout[8][P];
    int warp = threadIdx.x >> 5, lane = threadIdx.x & 31;
    int b = blockIdx.x * 8 + warp;
    if (b >= B) return;

    const float* row = states + (size_t)b * (L*D + 1);
#pragma unroll
    for (int i = 0; i < 4; i++) sx[warp][lane + 32*i] = row[1 + lane + 32*i];
    if (lane < L) sat[warp][lane] = __expf(g_logits[(size_t)b*L + lane]) * g_invden[lane];
    int phase = (int)row[0];
    __syncwarp();

    // y_p[d] and s_p
#pragma unroll
    for (int t = 0; t < 2; t++) {
        int idx = lane*2 + t;
        int p = idx >> 3, d = idx & 7;
        int i0 = pp[2*p], i1 = pp[2*p + 1];
        sy[warp][p][d] = sat[warp][i0]*sx[warp][i0*D + d] + sat[warp][i1]*sx[warp][i1*D + d];
    }
    if (lane < P) {
        int i0 = pp[2*lane], i1 = pp[2*lane + 1];
        ssum[warp][lane] = sat[warp][i0] + sat[warp][i1];
    }
    __syncwarp();

    // green (4 units per lane)
    float green[4];
    {
        float yd[D];
#pragma unroll
        for (int d = 0; d < D; d++) yd[d] = sy[warp][phase][d];
        float sp = ssum[warp][phase];
#pragma unroll
        for (int j = 0; j < 4; j++) {
            int u = lane + 32*j;
            float g = fmaf(sp, g_car[u], ar_b[u]);
#pragma unroll
            for (int d = 0; d < D; d++) g = fmaf(yd[d], g_WarT[d*U + u], g);
            green[j] = g;
        }
    }

    float wa[4][D], ca[4], ba[4], aw[4];
#pragma unroll
    for (int j = 0; j < 4; j++) {
        int u = lane + 32*j;
        ca[j] = g_caq[u];
        ba[j] = aq_b[u];
        aw[j] = aa_w[u];
#pragma unroll
        for (int d = 0; d < D; d++) wa[j][d] = g_WaqT[d*U + u];
    }
    float aab = *aa_b;

#pragma unroll
    for (int p = 0; p < P; p++) {
        float yd[D];
#pragma unroll
        for (int d = 0; d < D; d++) yd[d] = sy[warp][p][d];
        float sp = ssum[warp][p];
        float acc = 0.0f;
#pragma unroll
        for (int j = 0; j < 4; j++) {
            float pq = fmaf(sp, ca[j], ba[j]);
#pragma unroll
            for (int d = 0; d < D; d++) pq = fmaf(yd[d], wa[j][d], pq);
            acc = fmaf(fast_tanh(pq + green[j]), aw[j], acc);
        }
#pragma unroll
        for (int o = 16; o > 0; o >>= 1) acc += __shfl_down_sync(0xffffffffu, acc, o);
        if (lane == 0) sout[warp][p] = acc + aab;
    }
    __syncwarp();
    if (lane < P) out[(size_t)b*P + lane] = sout[warp][lane];
}

// ---------------------------------------------------------------------------
extern "C" void kernel_launch(void* const* d_in, const int* in_sizes, int n_in,
                              void* d_out, int out_size) {
    const float* states = (const float*)d_in[0];
    const float* le_w   = (const float*)d_in[1];
    const float* le_b   = (const float*)d_in[2];
    const float* sq_w   = (const float*)d_in[3];
    const float* sq_b   = (const float*)d_in[4];
    const float* sr_w   = (const float*)d_in[5];
    const float* sr_b   = (const float*)d_in[6];
    const float* sa_w   = (const float*)d_in[7];
    const float* sa_b   = (const float*)d_in[8];
    const float* aq_w   = (const float*)d_in[9];
    const float* aq_b   = (const float*)d_in[10];
    const float* ar_w   = (const float*)d_in[11];
    const float* ar_b   = (const float*)d_in[12];
    const float* aa_w   = (const float*)d_in[13];
    const float* aa_b   = (const float*)d_in[14];
    const int*   pp     = (const int*)d_in[15];
    float* out = (float*)d_out;

    int B = in_sizes[0] / (L*D + 1);
    if (B > BMAX) B = BMAX;
    int nb = (B + 7) / 8;

    k_compose<<<4, 128>>>(le_w, le_b, sq_w, sq_b, sr_w, sr_b, aq_w, ar_w);
    k_logits<<<nb, 256>>>(states, sa_w, sa_b, B);
    k_softmax_den<<<L, 256>>>(B);
    k_out<<<nb, 256>>>(states, aq_b, ar_b, aa_w, aa_b, pp, out, B);
}

// round 2
// speedup vs baseline: 1.3550x; 1.3550x over previous
#include <cuda_runtime.h>

#define BMAX 16384
#define L 16
#define D 8
#define U 128
#define P 8

// ---- composed-weight + softmax scratch (static device arrays; no allocs) ----
__device__ float g_WqT[D*U],  g_bq[U];   // sq_w composed with le_w (transposed [d][u])
__device__ float g_WrT[D*U],  g_br[U];   // sr_w composed
__device__ float g_WaqT[D*U], g_caq[U];  // aq_w composed (caq = aq_w@le_b)
__device__ float g_WarT[D*U], g_car[U];  // ar_w composed
__device__ float g_logits[(size_t)BMAX*L];
__device__ float g_invden[L];

// Native 5th-gen MUFU tanh: 1 instruction, abs err ~5e-4 (random-signed; damped
// by the 0.088-magnitude output weights and 128-term sums -> output ~3e-4).
__device__ __forceinline__ float fast_tanh(float x) {
    float y;
    asm("tanh.approx.f32 %0, %1;" : "=f"(y) : "f"(x));
    return y;
}

// Multi-value halving butterfly: reduces v[0..7] across all 32 lanes.
// After return, v[0] on lane r holds the full 32-lane sum of value index
// rev3(r&7) = 4*bit0 + 2*bit1 + 1*bit2.  Cost: 5 shfl + ~9 sel + ~7 add.
__device__ __forceinline__ void red8(float v[8], int lane) {
#pragma unroll
    for (int m = 1; m <= 4; m <<= 1) {
        int n = (m == 1) ? 8 : (m == 2) ? 4 : 2;
        int h = n >> 1;
        bool up = (lane & m) != 0;
#pragma unroll
        for (int i = 0; i < 4; i++) {
            if (i < h) {
                float send = up ? v[i] : v[i + h];
                float recv = __shfl_xor_sync(0xffffffffu, send, m);
                v[i] = (up ? v[i + h] : v[i]) + recv;
            }
        }
    }
    v[0] += __shfl_xor_sync(0xffffffffu, v[0], 8);
    v[0] += __shfl_xor_sync(0xffffffffu, v[0], 16);
}

__device__ __forceinline__ int rev3(int r) {
    return ((r & 1) << 2) | (r & 2) | ((r & 4) >> 2);
}

// ---------------------------------------------------------------------------
// Kernel 0: fold le_w/le_b through the four 128x128 linears.
// ---------------------------------------------------------------------------
__global__ void k_compose(const float* __restrict__ le_w, const float* __restrict__ le_b,
                          const float* __restrict__ sq_w, const float* __restrict__ sq_b,
                          const float* __restrict__ sr_w, const float* __restrict__ sr_b,
                          const float* __restrict__ aq_w,
                          const float* __restrict__ ar_w) {
    __shared__ float sle[U*D], sleb[U];
    int u = threadIdx.x;
#pragma unroll
    for (int d = 0; d < D; d++) sle[u*D + d] = le_w[u*D + d];
    sleb[u] = le_b[u];
    __syncthreads();

    int m = blockIdx.x;
    const float* W = (m == 0) ? sq_w : (m == 1) ? sr_w : (m == 2) ? aq_w : ar_w;

    float acc[D];
#pragma unroll
    for (int d = 0; d < D; d++) acc[d] = 0.0f;
    float ab = 0.0f;
    for (int k = 0; k < U; k++) {
        float w = W[u*U + k];
        ab = fmaf(w, sleb[k], ab);
#pragma unroll
        for (int d = 0; d < D; d++) acc[d] = fmaf(w, sle[k*D + d], acc[d]);
    }
    float* WT = (m == 0) ? g_WqT : (m == 1) ? g_WrT : (m == 2) ? g_WaqT : g_WarT;
#pragma unroll
    for (int d = 0; d < D; d++) WT[d*U + u] = acc[d];
    if      (m == 0) g_bq[u]  = ab + sq_b[u];
    else if (m == 1) g_br[u]  = ab + sr_b[u];
    else if (m == 2) g_caq[u] = ab;
    else             g_car[u] = ab;
}

// ---------------------------------------------------------------------------
// Kernel 1: attention logits. One warp per batch element, 8 warps/block.
// logit[b][l] = sa_b + sum_u tanh(ref[u] + x_l@WqT[.,u] + bq[u]) * sa_w[u]
// ---------------------------------------------------------------------------
__global__ void __launch_bounds__(256) k_logits(const float* __restrict__ states,
                                                const float* __restrict__ sa_w,
                                                const float* __restrict__ sa_b, int B) {
    __shared__ float sx[8][L*D];
    int warp = threadIdx.x >> 5, lane = threadIdx.x & 31;
    int b = blockIdx.x * 8 + warp;
    if (b >= B) return;

    const float* xs = states + (size_t)b * (L*D + 1) + 1;
#pragma unroll
    for (int i = 0; i < 4; i++) sx[warp][lane + 32*i] = xs[lane + 32*i];
    __syncwarp();

    // mean over 16 lanes per input dim (lanes 0..7 compute, broadcast)
    float mv = 0.0f;
    if (lane < D) {
#pragma unroll
        for (int l = 0; l < L; l++) mv += sx[warp][l*D + lane];
        mv *= (1.0f / 16.0f);
    }
    float mean[D];
#pragma unroll
    for (int d = 0; d < D; d++) mean[d] = __shfl_sync(0xffffffffu, mv, d);

    // ref + register-resident weights (4 units per lane)
    float wq[4][D], bq[4], sw[4], ref[4];
#pragma unroll
    for (int j = 0; j < 4; j++) {
        int u = lane + 32*j;
        bq[j] = g_bq[u];
        sw[j] = sa_w[u];
        float r = g_br[u];
#pragma unroll
        for (int d = 0; d < D; d++) {
            wq[j][d] = g_WqT[d*U + u];
            r = fmaf(mean[d], g_WrT[d*U + u], r);
        }
        ref[j] = r;
    }
    float sab = *sa_b;

#pragma unroll
    for (int g = 0; g < 2; g++) {
        float v[8];
#pragma unroll
        for (int i = 0; i < 8; i++) {
            int l = g*8 + i;
            float xl[D];
#pragma unroll
            for (int d = 0; d < D; d++) xl[d] = sx[warp][l*D + d];
            float acc = 0.0f;
#pragma unroll
            for (int j = 0; j < 4; j++) {
                float q = bq[j];
#pragma unroll
                for (int d = 0; d < D; d++) q = fmaf(xl[d], wq[j][d], q);
                acc = fmaf(fast_tanh(ref[j] + q), sw[j], acc);
            }
            v[i] = acc;
        }
        red8(v, lane);
        if (lane < 8) g_logits[(size_t)b*L + g*8 + rev3(lane)] = v[0] + sab;
    }
}

// ---------------------------------------------------------------------------
// Kernel 2: softmax denominator over the BATCH axis (one block per lane l).
// ---------------------------------------------------------------------------
__global__ void k_softmax_den(int B) {
    int l = blockIdx.x;
    int tid = threadIdx.x;
    float s = 0.0f;
    for (int b = tid; b < B; b += 256) s += __expf(g_logits[(size_t)b*L + l]);
    __shared__ float red[256];
    red[tid] = s;
    __syncthreads();
    for (int o = 128; o > 0; o >>= 1) {
        if (tid < o) red[tid] += red[tid + o];
        __syncthreads();
    }
    if (tid == 0) g_invden[l] = 1.0f / red[0];
}

// ---------------------------------------------------------------------------
// Kernel 3: output. One warp per batch element.
// ---------------------------------------------------------------------------
__global__ void __launch_bounds__(256) k_out(const float* __restrict__ states,
                                             const float* __restrict__ aq_b,
                                             const float* __restrict__ ar_b,
                                             const float* __restrict__ aa_w,
                                             const float* __restrict__ aa_b,
                                             const int*   __restrict__ pp,
                                             float* __restrict__ out, int B) {
    __shared__ float sx[8][L*D];
    __shared__ float sat[8][L];
    __shared__ float sy[8][P][D];
    __shared__ float ssum[8][P];
    int warp = threadIdx.x >> 5, lane = threadIdx.x & 31;
    int b = blockIdx.x * 8 + warp;
    if (b >= B) return;

    const float* row = states + (size_t)b * (L*D + 1);
#pragma unroll
    for (int i = 0; i < 4; i++) sx[warp][lane + 32*i] = row[1 + lane + 32*i];
    if (lane < L) sat[warp][lane] = __expf(g_logits[(size_t)b*L + lane]) * g_invden[lane];
    int phase = (int)row[0];
    __syncwarp();

    // y_p[d] and s_p
#pragma unroll
    for (int t = 0; t < 2; t++) {
        int idx = lane*2 + t;
        int p = idx >> 3, d = idx & 7;
        int i0 = pp[2*p], i1 = pp[2*p + 1];
        sy[warp][p][d] = sat[warp][i0]*sx[warp][i0*D + d] + sat[warp][i1]*sx[warp][i1*D + d];
    }
    if (lane < P) {
        int i0 = pp[2*lane], i1 = pp[2*lane + 1];
        ssum[warp][lane] = sat[warp][i0] + sat[warp][i1];
    }
    __syncwarp();

    // green (4 units per lane)
    float green[4];
    {
        float yd[D];
#pragma unroll
        for (int d = 0; d < D; d++) yd[d] = sy[warp][phase][d];
        float sp = ssum[warp][phase];
#pragma unroll
        for (int j = 0; j < 4; j++) {
            int u = lane + 32*j;
            float g = fmaf(sp, g_car[u], ar_b[u]);
#pragma unroll
            for (int d = 0; d < D; d++) g = fmaf(yd[d], g_WarT[d*U + u], g);
            green[j] = g;
        }
    }

    float wa[4][D], ca[4], ba[4], aw[4];
#pragma unroll
    for (int j = 0; j < 4; j++) {
        int u = lane + 32*j;
        ca[j] = g_caq[u];
        ba[j] = aq_b[u];
        aw[j] = aa_w[u];
#pragma unroll
        for (int d = 0; d < D; d++) wa[j][d] = g_WaqT[d*U + u];
    }
    float aab = *aa_b;

    float acc[P];
#pragma unroll
    for (int p = 0; p < P; p++) {
        float yd[D];
#pragma unroll
        for (int d = 0; d < D; d++) yd[d] = sy[warp][p][d];
        float sp = ssum[warp][p];
        float a = 0.0f;
#pragma unroll
        for (int j = 0; j < 4; j++) {
            float pq = fmaf(sp, ca[j], ba[j]);
#pragma unroll
            for (int d = 0; d < D; d++) pq = fmaf(yd[d], wa[j][d], pq);
            a = fmaf(fast_tanh(pq + green[j]), aw[j], a);
        }
        acc[p] = a;
    }
    red8(acc, lane);
    if (lane < 8) out[(size_t)b*P + rev3(lane)] = acc[0] + aab;
}

// ---------------------------------------------------------------------------
extern "C" void kernel_launch(void* const* d_in, const int* in_sizes, int n_in,
                              void* d_out, int out_size) {
    const float* states = (const float*)d_in[0];
    const float* le_w   = (const float*)d_in[1];
    const float* le_b   = (const float*)d_in[2];
    const float* sq_w   = (const float*)d_in[3];
    const float* sq_b   = (const float*)d_in[4];
    const float* sr_w   = (const float*)d_in[5];
    const float* sr_b   = (const float*)d_in[6];
    const float* sa_w   = (const float*)d_in[7];
    const float* sa_b   = (const float*)d_in[8];
    const float* aq_w   = (const float*)d_in[9];
    const float* aq_b   = (const float*)d_in[10];
    const float* ar_w   = (const float*)d_in[11];
    const float* ar_b   = (const float*)d_in[12];
    const float* aa_w   = (const float*)d_in[13];
    const float* aa_b   = (const float*)d_in[14];
    const int*   pp     = (const int*)d_in[15];
    float* out = (float*)d_out;

    int B = in_sizes[0] / (L*D + 1);
    if (B > BMAX) B = BMAX;
    int nb = (B + 7) / 8;

    k_compose<<<4, 128>>>(le_w, le_b, sq_w, sq_b, sr_w, sr_b, aq_w, ar_w);
    k_logits<<<nb, 256>>>(states, sa_w, sa_b, B);
    k_softmax_den<<<L, 256>>>(B);
    k_out<<<nb, 256>>>(states, aq_b, ar_b, aa_w, aa_b, pp, out, B);
}